// round 2
// baseline (speedup 1.0000x reference)
#include <cuda_runtime.h>

// SpanIndexEncoder: out[t,f] = sum over nodes n (n < num_nodes, start_n <= t <= end_n) of emb[n,f]
// Difference-array scatter + 3-level chunked prefix scan along t.
//   T = 8192 tokens, N = 8192 max nodes, F = 256 features.

#define T_MAX  8192
#define N_MAX  8192
#define FDIM   256
#define CHUNK  32
#define NCHUNK (T_MAX / CHUNK)   // 256

// Scratch (allocation-free): 8 MB diff + 256 KB chunk sums + 256 KB chunk prefixes.
__device__ float g_diff[T_MAX * FDIM];
__device__ float g_S[NCHUNK * FDIM];
__device__ float g_P[NCHUNK * FDIM];

// ---------------------------------------------------------------------------
// K1: zero the diff array (must be re-zeroed every replay).
// ---------------------------------------------------------------------------
__global__ void k_zero() {
    int i = blockIdx.x * blockDim.x + threadIdx.x;
    reinterpret_cast<float4*>(g_diff)[i] = make_float4(0.f, 0.f, 0.f, 0.f);
}

// ---------------------------------------------------------------------------
// K2: scatter. One block per node, one thread per feature.
//   diff[start][f]  += emb[n][f]
//   diff[end+1][f]  -= emb[n][f]   (skip if end+1 == T_MAX)
// Coalesced 128B REDG per warp, spread addresses -> low L2-atomic contention.
// ---------------------------------------------------------------------------
__global__ void k_scatter(const float* __restrict__ emb,
                          const int*   __restrict__ starts,
                          const int*   __restrict__ ends,
                          const int*   __restrict__ num_nodes_p) {
    int n = blockIdx.x;
    if (n >= *num_nodes_p) return;
    int s = starts[n];
    int e = ends[n];
    if (s > e) return;                       // empty span contributes nothing
    int f = threadIdx.x;
    float v = emb[n * FDIM + f];
    atomicAdd(&g_diff[s * FDIM + f], v);
    int e1 = e + 1;
    if (e1 < T_MAX) atomicAdd(&g_diff[e1 * FDIM + f], -v);
}

// ---------------------------------------------------------------------------
// K3: per-chunk column sums. Block c, thread f: S[c][f] = sum of 32 rows.
// Independent coalesced L2-resident loads -> deep MLP.
// ---------------------------------------------------------------------------
__global__ void k_sums() {
    int c = blockIdx.x;
    int f = threadIdx.x;
    const float* base = g_diff + c * CHUNK * FDIM + f;
    float s = 0.f;
#pragma unroll
    for (int t = 0; t < CHUNK; t++) s += base[t * FDIM];
    g_S[c * FDIM + f] = s;
}

// ---------------------------------------------------------------------------
// K3b: exclusive prefix over chunks, per feature.
//   P[c][f] = sum of S[0..c-1][f].
// 8 blocks x 32 threads; each thread owns one feature. 256 L2-resident loads
// (independent addresses, prefetchable), serial chain is 256 FADDs only.
// ---------------------------------------------------------------------------
__global__ void k_scan_top() {
    int f = blockIdx.x * 32 + threadIdx.x;
    float acc = 0.f;
#pragma unroll 8
    for (int cc = 0; cc < NCHUNK; cc++) {
        g_P[cc * FDIM + f] = acc;
        acc += g_S[cc * FDIM + f];
    }
}

// ---------------------------------------------------------------------------
// K4: final scan. Block c, thread f:
//   acc = P[c][f]  (one L2 hit)
//   then serial inclusive scan of 32 rows, writing out (coalesced stores).
// ---------------------------------------------------------------------------
__global__ void k_out(float* __restrict__ out) {
    int c = blockIdx.x;
    int f = threadIdx.x;
    float acc = g_P[c * FDIM + f];
    const float* base = g_diff + c * CHUNK * FDIM + f;
    float*       ob   = out    + c * CHUNK * FDIM + f;
#pragma unroll
    for (int t = 0; t < CHUNK; t++) {
        acc += base[t * FDIM];
        ob[t * FDIM] = acc;
    }
}

// ---------------------------------------------------------------------------
// Inputs (metadata order): embedding f32 [8192*256], node_span_starts i32
// [8192], node_span_ends i32 [8192], num_nodes i32 [1]. Output f32 [8192*256].
// ---------------------------------------------------------------------------
extern "C" void kernel_launch(void* const* d_in, const int* in_sizes, int n_in,
                              void* d_out, int out_size) {
    const float* emb    = (const float*)d_in[0];
    const int*   starts = (const int*)d_in[1];
    const int*   ends   = (const int*)d_in[2];
    const int*   nn     = (const int*)d_in[3];
    float*       out    = (float*)d_out;

    // zero 8 MB diff: T_MAX*FDIM/4 float4 = 524288 -> 2048 blocks x 256
    k_zero<<<(T_MAX * FDIM / 4) / 256, 256>>>();
    k_scatter<<<N_MAX, FDIM>>>(emb, starts, ends, nn);
    k_sums<<<NCHUNK, FDIM>>>();
    k_scan_top<<<FDIM / 32, 32>>>();
    k_out<<<NCHUNK, FDIM>>>(out);
}

// round 3
// speedup vs baseline: 3.4412x; 3.4412x over previous
#include <cuda_runtime.h>

// SpanIndexEncoder: out[t,f] = sum over nodes n (n < num_nodes, start_n <= t <= end_n) of emb[n,f]
// Difference-array scatter + 3-level chunked prefix scan along t.
//   T = 8192 tokens, N = 8192 max nodes, F = 256 features.

#define T_MAX  8192
#define N_MAX  8192
#define FDIM   256
#define CHUNK  32
#define NCHUNK (T_MAX / CHUNK)   // 256

// Scratch (allocation-free): 8 MB diff + 256 KB chunk sums + 256 KB chunk prefixes.
__device__ float g_diff[T_MAX * FDIM];
__device__ float g_S[NCHUNK * FDIM];
__device__ float g_P[NCHUNK * FDIM];

// ---------------------------------------------------------------------------
// K1: zero the diff array (must be re-zeroed every replay).
// ---------------------------------------------------------------------------
__global__ void k_zero() {
    int i = blockIdx.x * blockDim.x + threadIdx.x;
    reinterpret_cast<float4*>(g_diff)[i] = make_float4(0.f, 0.f, 0.f, 0.f);
}

// ---------------------------------------------------------------------------
// K2: scatter. One block per node, one thread per feature.
//   diff[start][f]  += emb[n][f]
//   diff[end+1][f]  -= emb[n][f]   (skip if end+1 == T_MAX)
// Coalesced 128B REDG per warp, spread addresses -> low L2-atomic contention.
// ---------------------------------------------------------------------------
__global__ void k_scatter(const float* __restrict__ emb,
                          const int*   __restrict__ starts,
                          const int*   __restrict__ ends,
                          const int*   __restrict__ num_nodes_p) {
    int n = blockIdx.x;
    if (n >= *num_nodes_p) return;
    int s = starts[n];
    int e = ends[n];
    if (s > e) return;                       // empty span contributes nothing
    int f = threadIdx.x;
    float v = emb[n * FDIM + f];
    atomicAdd(&g_diff[s * FDIM + f], v);
    int e1 = e + 1;
    if (e1 < T_MAX) atomicAdd(&g_diff[e1 * FDIM + f], -v);
}

// ---------------------------------------------------------------------------
// K3: per-chunk column sums. Block c, thread f: S[c][f] = sum of 32 rows.
// Independent coalesced L2-resident loads -> deep MLP.
// ---------------------------------------------------------------------------
__global__ void k_sums() {
    int c = blockIdx.x;
    int f = threadIdx.x;
    const float* base = g_diff + c * CHUNK * FDIM + f;
    float s = 0.f;
#pragma unroll
    for (int t = 0; t < CHUNK; t++) s += base[t * FDIM];
    g_S[c * FDIM + f] = s;
}

// ---------------------------------------------------------------------------
// K3b: PARALLEL exclusive prefix over chunks, per feature.
// One block per feature f (grid=256); thread c in [0,256) owns chunk c.
// Warp-shuffle inclusive scan + cross-warp smem combine. No memory latency
// in the dependence chain (fixes the 115us serial-walk disaster of R2).
// ---------------------------------------------------------------------------
__global__ void k_scan() {
    int f    = blockIdx.x;
    int c    = threadIdx.x;
    int lane = c & 31;
    int wid  = c >> 5;

    float v = g_S[c * FDIM + f];

    // inclusive scan within warp
    float x = v;
#pragma unroll
    for (int d = 1; d < 32; d <<= 1) {
        float u = __shfl_up_sync(0xFFFFFFFFu, x, d);
        if (lane >= d) x += u;
    }

    __shared__ float wsum[8];
    if (lane == 31) wsum[wid] = x;
    __syncthreads();

    if (wid == 0 && lane < 8) {
        float y = wsum[lane];
#pragma unroll
        for (int d = 1; d < 8; d <<= 1) {
            float u = __shfl_up_sync(0xFFu, y, d);
            if (lane >= d) y += u;
        }
        wsum[lane] = y;   // inclusive warp sums
    }
    __syncthreads();

    float offset = (wid > 0) ? wsum[wid - 1] : 0.f;
    float incl = x + offset;
    g_P[c * FDIM + f] = incl - v;   // exclusive prefix
}

// ---------------------------------------------------------------------------
// K4: final scan. Block c, thread f:
//   acc = P[c][f]  (one L2 hit)
//   then serial inclusive scan of 32 rows, writing out (coalesced stores).
// ---------------------------------------------------------------------------
__global__ void k_out(float* __restrict__ out) {
    int c = blockIdx.x;
    int f = threadIdx.x;
    float acc = g_P[c * FDIM + f];
    const float* base = g_diff + c * CHUNK * FDIM + f;
    float*       ob   = out    + c * CHUNK * FDIM + f;
#pragma unroll
    for (int t = 0; t < CHUNK; t++) {
        acc += base[t * FDIM];
        ob[t * FDIM] = acc;
    }
}

// ---------------------------------------------------------------------------
// Inputs (metadata order): embedding f32 [8192*256], node_span_starts i32
// [8192], node_span_ends i32 [8192], num_nodes i32 [1]. Output f32 [8192*256].
// ---------------------------------------------------------------------------
extern "C" void kernel_launch(void* const* d_in, const int* in_sizes, int n_in,
                              void* d_out, int out_size) {
    const float* emb    = (const float*)d_in[0];
    const int*   starts = (const int*)d_in[1];
    const int*   ends   = (const int*)d_in[2];
    const int*   nn     = (const int*)d_in[3];
    float*       out    = (float*)d_out;

    // zero 8 MB diff: T_MAX*FDIM/4 float4 = 524288 -> 2048 blocks x 256
    k_zero<<<(T_MAX * FDIM / 4) / 256, 256>>>();
    k_scatter<<<N_MAX, FDIM>>>(emb, starts, ends, nn);
    k_sums<<<NCHUNK, FDIM>>>();
    k_scan<<<FDIM, NCHUNK>>>();
    k_out<<<NCHUNK, FDIM>>>(out);
}